// round 16
// baseline (speedup 1.0000x reference)
#include <cuda_runtime.h>
#include <cuda_bf16.h>
#include <cstdint>
#include <math.h>

// Problem constants
#define BB 8
#define NN 256
#define FF 256
#define HH 128
#define TT 256
#define G4 512           // 4*H gates
#define ROWS (BB*NN)     // 2048

// ---------------- scratch (device globals; no allocation allowed) ----------------
__device__ float g_S[BB*FF];                 // column sums
__device__ float g_ctmp[4*BB*NN*FF];         // cheb split-K partials (4)
__device__ float g_cout[BB*NN*FF];           // cheb out (layer1 input)
__device__ float g_gin[ROWS*1024];           // input gates, both dirs: [B*T][1024]
__device__ float g_h1[BB*NN*2*HH];           // layer1 concat output
__device__ float g_h2[BB*NN*2*HH];           // layer2 concat output

typedef unsigned long long ull;

// ---------------- small helpers ----------------
__device__ __forceinline__ float blocksum256(float v, volatile float* red) {
    #pragma unroll
    for (int o = 16; o; o >>= 1) v += __shfl_xor_sync(0xffffffffu, v, o);
    if ((threadIdx.x & 31) == 0) red[threadIdx.x >> 5] = v;
    __syncthreads();
    float s = 0.f;
    #pragma unroll
    for (int i = 0; i < 8; i++) s += red[i];
    return s;
}

__device__ __forceinline__ unsigned smem_u32(const void* p) {
    unsigned a;
    asm("{ .reg .u64 t; cvta.to.shared.u64 t, %1; cvt.u32.u64 %0, t; }"
        : "=r"(a) : "l"(p));
    return a;
}

// fast activations: __expf/__fdividef (rel err ~1e-7, fine vs 1e-3 threshold)
__device__ __forceinline__ float fsigmoid(float x) {
    return __fdividef(1.0f, 1.0f + __expf(-x));
}
__device__ __forceinline__ float ftanh(float x) {
    return 1.0f - __fdividef(2.0f, __expf(2.0f * x) + 1.0f);
}

#define MBAR_INIT(adr, cnt) \
    asm volatile("mbarrier.init.shared.b64 [%0], %1;" :: "r"(adr), "r"(cnt) : "memory")

#define MBAR_EXPECT_TX(adr, bytes) \
    asm volatile("mbarrier.arrive.expect_tx.shared.b64 _, [%0], %1;" \
                 :: "r"(adr), "r"(bytes) : "memory")

#define MBAR_WAIT_PARITY(adr, parity) do {                                        \
    unsigned _done;                                                               \
    asm volatile("{\n\t.reg .pred p;\n\t"                                         \
        "mbarrier.try_wait.parity.acquire.cluster.shared::cta.b64 p, [%1], %2;\n\t" \
        "selp.b32 %0, 1, 0, p;\n\t}"                                              \
        : "=r"(_done) : "r"(adr), "r"(parity) : "memory");                        \
    while (!_done) {                                                              \
        asm volatile("{\n\t.reg .pred p;\n\t"                                     \
            "mbarrier.try_wait.parity.acquire.cluster.shared::cta.b64 p, [%1], %2, 0x989680;\n\t" \
            "selp.b32 %0, 1, 0, p;\n\t}"                                          \
            : "=r"(_done) : "r"(adr), "r"(parity) : "memory");                    \
    } } while (0)

// ---------------- colsum + TG fill (merged launch) ----------------
__global__ void colsum_fill_kernel(const float* __restrict__ x, float* __restrict__ S,
                                   float* __restrict__ tg) {
    if (blockIdx.x < BB) {
        int b = blockIdx.x, f = threadIdx.x;
        float s = 0.f;
        const float* xb = x + (size_t)b * NN * FF + f;
        #pragma unroll 4
        for (int n = 0; n < NN; n++) s += xb[(size_t)n * FF];
        S[b * FF + f] = s;
    } else {
        // TG = exact constant (LayerNorm(1) degenerates; softmax of const rows)
        int i = (blockIdx.x - BB) * blockDim.x + threadIdx.x;
        const float q = 1.0f / 256.0f;
        ((float4*)tg)[i] = make_float4(q, q, q, q);
    }
}

// ---------------- 128(M)x64(N)-tile GEMM, BK=32, 2 CTAs/SM (gin GEMMs) --------
// C[M,N] = A[M,K] @ B[N,K]^T + bias0 + bias1. 256 threads, 4x4 f32x2-row-pair
// outputs each. BK=32: 8 tiles instead of 16 -> half the syncs, longer FFMA2
// runs to hide LDS latency. smem 48KB/CTA (96KB at occ 2).
__global__ __launch_bounds__(256, 2)
void gemm64n(const float* __restrict__ A, const float* __restrict__ B,
             float* __restrict__ C, int M, int N, int K,
             const float* __restrict__ bias0, const float* __restrict__ bias1)
{
    const int BK = 32;
    __shared__ float As[2][BK][128];
    __shared__ float Bs[2][BK][64];
    int tid = threadIdx.x;
    int tx = tid & 15, ty = tid >> 4;
    int bm = blockIdx.y * 128, bn = blockIdx.x * 64;

    // A tile (128 rows x 32 k = 4096 floats): 4 float4/thread.
    //   quad qi = 4*tid+i: row = qi>>3, kf = (qi&7)*4
    // B tile (64 x 32 = 2048 floats): 2 float4/thread, quad qi = 2*tid+i.
    const int ntiles = K / BK;
    float4 pa[4], pb[2];
    auto loadTile = [&](int k0) {
        #pragma unroll
        for (int i = 0; i < 4; i++) {
            int qi = 4 * tid + i;
            pa[i] = *(const float4*)(A + (size_t)(bm + (qi >> 3)) * K + k0 + (qi & 7) * 4);
        }
        #pragma unroll
        for (int i = 0; i < 2; i++) {
            int qi = 2 * tid + i;
            pb[i] = *(const float4*)(B + (size_t)(bn + (qi >> 3)) * K + k0 + (qi & 7) * 4);
        }
    };
    auto stash = [&](int st) {
        #pragma unroll
        for (int i = 0; i < 4; i++) {
            int qi = 4 * tid + i;
            int r = qi >> 3, kf = (qi & 7) * 4;
            As[st][kf + 0][r] = pa[i].x; As[st][kf + 1][r] = pa[i].y;
            As[st][kf + 2][r] = pa[i].z; As[st][kf + 3][r] = pa[i].w;
        }
        #pragma unroll
        for (int i = 0; i < 2; i++) {
            int qi = 2 * tid + i;
            int r = qi >> 3, kf = (qi & 7) * 4;
            Bs[st][kf + 0][r] = pb[i].x; Bs[st][kf + 1][r] = pb[i].y;
            Bs[st][kf + 2][r] = pb[i].z; Bs[st][kf + 3][r] = pb[i].w;
        }
    };

    loadTile(0);
    stash(0);
    __syncthreads();

    ull acc[4][4];
    #pragma unroll
    for (int i = 0; i < 4; i++)
        #pragma unroll
        for (int j = 0; j < 4; j++) acc[i][j] = 0ull;

    for (int kt = 0; kt < ntiles; kt++) {
        int st = kt & 1;
        if (kt + 1 < ntiles) loadTile((kt + 1) * BK);
        #pragma unroll
        for (int k = 0; k < BK; k++) {
            const float* ar = &As[st][k][ty * 8];
            const float* br2 = &Bs[st][k][tx * 4];
            ull ap[4], bd[4];
            #pragma unroll
            for (int i = 0; i < 4; i++) {
                float2 a2 = *(const float2*)(ar + 2 * i);
                asm("mov.b64 %0, {%1, %2};" : "=l"(ap[i]) : "f"(a2.x), "f"(a2.y));
            }
            #pragma unroll
            for (int i = 0; i < 2; i++) {
                float2 b2 = *(const float2*)(br2 + 2 * i);
                asm("mov.b64 %0, {%1, %1};" : "=l"(bd[2 * i])     : "f"(b2.x));
                asm("mov.b64 %0, {%1, %1};" : "=l"(bd[2 * i + 1]) : "f"(b2.y));
            }
            #pragma unroll
            for (int i = 0; i < 4; i++)
                #pragma unroll
                for (int j = 0; j < 4; j++)
                    asm("fma.rn.f32x2 %0, %1, %2, %3;"
                        : "=l"(acc[i][j]) : "l"(ap[i]), "l"(bd[j]), "l"(acc[i][j]));
        }
        if (kt + 1 < ntiles) stash(st ^ 1);
        __syncthreads();
    }

    float bsum[4];
    #pragma unroll
    for (int j = 0; j < 4; j++) {
        int col = bn + tx * 4 + j;
        bsum[j] = (bias0 ? bias0[col] : 0.f) + (bias1 ? bias1[col] : 0.f);
    }
    #pragma unroll
    for (int i = 0; i < 4; i++) {
        float lov[4], hiv[4];
        #pragma unroll
        for (int j = 0; j < 4; j++) {
            float lo, hi;
            asm("mov.b64 {%0, %1}, %2;" : "=f"(lo), "=f"(hi) : "l"(acc[i][j]));
            lov[j] = lo + bsum[j]; hiv[j] = hi + bsum[j];
        }
        int row = bm + ty * 8 + 2 * i;
        int col = bn + tx * 4;
        *(float4*)(C + (size_t)row * N + col)       = make_float4(lov[0], lov[1], lov[2], lov[3]);
        *(float4*)(C + (size_t)(row + 1) * N + col) = make_float4(hiv[0], hiv[1], hiv[2], hiv[3]);
    }
}

// ---------------- cheb split-K GEMM (R10 version, verbatim) -------
__global__ __launch_bounds__(256)
void gemm128_cheb(const float* __restrict__ A, const float* __restrict__ S,
                  const float* __restrict__ B, float* __restrict__ C,
                  int M, int N)
{
    const int BK = 16;
    __shared__ float As[2][BK][128];
    __shared__ float Bs[2][BK][128];
    int tid = threadIdx.x;
    int tx = tid & 15, ty = tid >> 4;
    int bm = blockIdx.y * 128, bn = blockIdx.x * 128;
    int kbeg = blockIdx.z * 128;
    C += (size_t)blockIdx.z * M * N;

    int r0 = (2 * tid) >> 2,     kf0 = ((2 * tid) & 3) * 4;
    int r1 = (2 * tid + 1) >> 2, kf1 = ((2 * tid + 1) & 3) * 4;
    int kr = tid >> 4, cq = (tid & 15) * 8;

    auto loadA4 = [&](int k0, int rr, int kf) -> float4 {
        int row = bm + rr;
        int kk = k0 + kf;
        if (kk >= 256) {
            kk -= 256;
            float4 xv = *(const float4*)(A + (size_t)row * 256 + kk);
            float4 sv = *(const float4*)(S + (row >> 8) * 256 + kk);
            const float q = 1.0f / 256.0f;
            return make_float4(0.5f * (xv.x + q * sv.x), 0.5f * (xv.y + q * sv.y),
                               0.5f * (xv.z + q * sv.z), 0.5f * (xv.w + q * sv.w));
        }
        return *(const float4*)(A + (size_t)row * 256 + kk);
    };
    auto stash = [&](int st, float4 a0, float4 a1, float4 b0, float4 b1) {
        As[st][kf0 + 0][r0] = a0.x; As[st][kf0 + 1][r0] = a0.y;
        As[st][kf0 + 2][r0] = a0.z; As[st][kf0 + 3][r0] = a0.w;
        As[st][kf1 + 0][r1] = a1.x; As[st][kf1 + 1][r1] = a1.y;
        As[st][kf1 + 2][r1] = a1.z; As[st][kf1 + 3][r1] = a1.w;
        *(float4*)&Bs[st][kr][cq]     = b0;
        *(float4*)&Bs[st][kr][cq + 4] = b1;
    };

    const int ntiles = 128 / BK;  // 8
    stash(0, loadA4(kbeg, r0, kf0), loadA4(kbeg, r1, kf1),
             *(const float4*)(B + (size_t)(kbeg + kr) * N + bn + cq),
             *(const float4*)(B + (size_t)(kbeg + kr) * N + bn + cq + 4));
    __syncthreads();

    ull acc[4][8];
    #pragma unroll
    for (int i = 0; i < 4; i++)
        #pragma unroll
        for (int j = 0; j < 8; j++) acc[i][j] = 0ull;

    for (int kt = 0; kt < ntiles; kt++) {
        int st = kt & 1;
        float4 an0, an1, bn0, bn1;
        if (kt + 1 < ntiles) {
            int k0 = kbeg + (kt + 1) * BK;
            an0 = loadA4(k0, r0, kf0); an1 = loadA4(k0, r1, kf1);
            bn0 = *(const float4*)(B + (size_t)(k0 + kr) * N + bn + cq);
            bn1 = *(const float4*)(B + (size_t)(k0 + kr) * N + bn + cq + 4);
        }
        #pragma unroll
        for (int k = 0; k < BK; k++) {
            const float* ar = &As[st][k][ty * 8];
            const float* br = &Bs[st][k][tx * 8];
            ull ap[4], bd[8];
            #pragma unroll
            for (int i = 0; i < 4; i++) {
                float2 a2 = *(const float2*)(ar + 2 * i);
                asm("mov.b64 %0, {%1, %2};" : "=l"(ap[i]) : "f"(a2.x), "f"(a2.y));
            }
            #pragma unroll
            for (int i = 0; i < 4; i++) {
                float2 b2 = *(const float2*)(br + 2 * i);
                asm("mov.b64 %0, {%1, %1};" : "=l"(bd[2 * i])     : "f"(b2.x));
                asm("mov.b64 %0, {%1, %1};" : "=l"(bd[2 * i + 1]) : "f"(b2.y));
            }
            #pragma unroll
            for (int i = 0; i < 4; i++)
                #pragma unroll
                for (int j = 0; j < 8; j++)
                    asm("fma.rn.f32x2 %0, %1, %2, %3;"
                        : "=l"(acc[i][j]) : "l"(ap[i]), "l"(bd[j]), "l"(acc[i][j]));
        }
        if (kt + 1 < ntiles)
            stash(st ^ 1, an0, an1, bn0, bn1);
        __syncthreads();
    }

    #pragma unroll
    for (int i = 0; i < 4; i++) {
        float lov[8], hiv[8];
        #pragma unroll
        for (int j = 0; j < 8; j++) {
            float lo, hi;
            asm("mov.b64 {%0, %1}, %2;" : "=f"(lo), "=f"(hi) : "l"(acc[i][j]));
            lov[j] = lo; hiv[j] = hi;
        }
        int row = bm + ty * 8 + 2 * i;
        int col = bn + tx * 8;
        *(float4*)(C + (size_t)row * N + col)           = make_float4(lov[0], lov[1], lov[2], lov[3]);
        *(float4*)(C + (size_t)row * N + col + 4)       = make_float4(lov[4], lov[5], lov[6], lov[7]);
        *(float4*)(C + (size_t)(row + 1) * N + col)     = make_float4(hiv[0], hiv[1], hiv[2], hiv[3]);
        *(float4*)(C + (size_t)(row + 1) * N + col + 4) = make_float4(hiv[4], hiv[5], hiv[6], hiv[7]);
    }
}

// ---------------- LayerNorm over 256 elems per row ----------------
__global__ __launch_bounds__(256)
void ln256_kernel(const float* __restrict__ x, const float* __restrict__ g,
                  const float* __restrict__ bt, float* __restrict__ y)
{
    __shared__ float red1[8];
    __shared__ float red2[8];
    size_t row = blockIdx.x;
    float v = x[row * 256 + threadIdx.x];
    float m = blocksum256(v, red1) * (1.0f / 256.0f);
    float d = v - m;
    float var = blocksum256(d * d, red2) * (1.0f / 256.0f);
    float r = rsqrtf(var + 1e-5f);
    y[row * 256 + threadIdx.x] = d * r * g[threadIdx.x] + bt[threadIdx.x];
}

// LN over sum of 4 split-K partials + bias (cheb path)
__global__ __launch_bounds__(256)
void ln256_sum4_kernel(const float* __restrict__ p, const float* __restrict__ bias,
                       const float* __restrict__ g, const float* __restrict__ bt,
                       float* __restrict__ y)
{
    __shared__ float red1[8];
    __shared__ float red2[8];
    size_t row = blockIdx.x;
    size_t idx = row * 256 + threadIdx.x;
    const size_t P = (size_t)ROWS * 256;
    float v = (p[idx] + p[idx + P]) + (p[idx + 2 * P] + p[idx + 3 * P]) + bias[threadIdx.x];
    float m = blocksum256(v, red1) * (1.0f / 256.0f);
    float d = v - m;
    float var = blocksum256(d * d, red2) * (1.0f / 256.0f);
    float r = rsqrtf(var + 1e-5f);
    y[idx] = d * r * g[threadIdx.x] + bt[threadIdx.x];
}

// ---------------- LSTM scan (R11 best-measured version, FROZEN) ----------------
__global__ void __launch_bounds__(128, 1) __cluster_dims__(4, 1, 1)
lstm_scan_cluster(const float* __restrict__ gin, const float* __restrict__ whh,
                  float* __restrict__ hout)
{
    __shared__ __align__(16) float hsh[2][HH];
    __shared__ __align__(16) float gb[2][G4];
    __shared__ __align__(8) ull mbar[2];

    int tid = threadIdx.x;
    unsigned rank;
    asm("mov.u32 %0, %%cluster_ctarank;" : "=r"(rank));
    int pair = blockIdx.x >> 2;
    int b = pair >> 1, d = pair & 1;
    int gate = (int)rank * 128 + tid;

    ull w[64];
    const float2* wrow = (const float2*)(whh + ((size_t)d * G4 + gate) * HH);
    #pragma unroll
    for (int i = 0; i < 64; i++) {
        float2 t2 = wrow[i];
        asm("mov.b64 %0, {%1, %2};" : "=l"(w[i]) : "f"(t2.x), "f"(t2.y));
    }

    const float* gp = gin + ((size_t)b * TT) * 1024 + d * 512 + gate;

    hsh[0][tid] = 0.f;

    unsigned hadr0 = smem_u32(&hsh[0][0]);
    unsigned hadr1 = smem_u32(&hsh[1][0]);
    unsigned mloc[2] = { smem_u32(&mbar[0]), smem_u32(&mbar[1]) };
    unsigned gadr[2][4], madr[2][4];
    #pragma unroll
    for (int par = 0; par < 2; par++) {
        unsigned la = smem_u32(&gb[par][gate]);
        #pragma unroll
        for (int peer = 0; peer < 4; peer++) {
            asm("mapa.shared::cluster.u32 %0, %1, %2;"
                : "=r"(gadr[par][peer]) : "r"(la), "r"(peer));
            asm("mapa.shared::cluster.u32 %0, %1, %2;"
                : "=r"(madr[par][peer]) : "r"(mloc[par]), "r"(peer));
        }
    }

    if (tid == 0) {
        MBAR_INIT(mloc[0], 1);
        MBAR_INIT(mloc[1], 1);
        MBAR_EXPECT_TX(mloc[0], 2048);   // step 0
        MBAR_EXPECT_TX(mloc[1], 2048);   // step 1
    }
    __syncthreads();
    asm volatile("barrier.cluster.arrive.aligned;" ::: "memory");
    asm volatile("barrier.cluster.wait.aligned;" ::: "memory");

    int ph0 = 0, ph1 = 0;
    float c = 0.f;
    int t = d ? (TT - 1) : 0;
    const int tstep = d ? -1 : 1;
    float gcur = gp[(size_t)t * 1024];

    for (int s = 0; s < TT; s++) {
        int par = s & 1;
        unsigned hadr = par ? hadr1 : hadr0;   // dot reads hsh[s&1]

        ull a0 = 0ull, a1 = 0ull, a2 = 0ull, a3 = 0ull;
        #pragma unroll
        for (int i = 0; i < 64; i += 4) {
            ull h0, h1, h2, h3;
            asm volatile("ld.shared.v2.b64 {%0, %1}, [%2];"
                         : "=l"(h0), "=l"(h1) : "r"(hadr + i * 8));
            asm volatile("ld.shared.v2.b64 {%0, %1}, [%2];"
                         : "=l"(h2), "=l"(h3) : "r"(hadr + i * 8 + 16));
            asm("fma.rn.f32x2 %0, %1, %2, %3;" : "=l"(a0) : "l"(w[i + 0]), "l"(h0), "l"(a0));
            asm("fma.rn.f32x2 %0, %1, %2, %3;" : "=l"(a1) : "l"(w[i + 1]), "l"(h1), "l"(a1));
            asm("fma.rn.f32x2 %0, %1, %2, %3;" : "=l"(a2) : "l"(w[i + 2]), "l"(h2), "l"(a2));
            asm("fma.rn.f32x2 %0, %1, %2, %3;" : "=l"(a3) : "l"(w[i + 3]), "l"(h3), "l"(a3));
        }
        float x0, y0, x1, y1, x2, y2, x3, y3;
        asm("mov.b64 {%0, %1}, %2;" : "=f"(x0), "=f"(y0) : "l"(a0));
        asm("mov.b64 {%0, %1}, %2;" : "=f"(x1), "=f"(y1) : "l"(a1));
        asm("mov.b64 {%0, %1}, %2;" : "=f"(x2), "=f"(y2) : "l"(a2));
        asm("mov.b64 {%0, %1}, %2;" : "=f"(x3), "=f"(y3) : "l"(a3));
        float v = gcur + ((x0 + y0) + (x1 + y1)) + ((x2 + y2) + (x3 + y3));

        unsigned vbits = __float_as_uint(v);
        #pragma unroll
        for (int peer = 0; peer < 4; peer++) {
            asm volatile(
                "st.async.shared::cluster.mbarrier::complete_tx::bytes.b32 [%0], %1, [%2];"
                :: "r"(gadr[par][peer]), "r"(vbits), "r"(madr[par][peer]) : "memory");
        }

        float gnext = 0.f;
        if (s + 1 < TT) gnext = gp[(size_t)(t + tstep) * 1024];

        unsigned mb = par ? mloc[1] : mloc[0];
        int phv = par ? ph1 : ph0;
        MBAR_WAIT_PARITY(mb, phv);
        if (par) ph1 ^= 1; else ph0 ^= 1;
        if (tid == 0 && s + 2 < TT) MBAR_EXPECT_TX(mb, 2048);

        float ig = fsigmoid(gb[par][tid]);
        float fg = fsigmoid(gb[par][tid + 128]);
        float gg = ftanh(gb[par][tid + 256]);
        float og = fsigmoid(gb[par][tid + 384]);
        c = fg * c + ig * gg;
        float h = og * ftanh(c);
        hsh[par ^ 1][tid] = h;    // write the OTHER buffer (next step reads it)
        if (rank == 0)
            hout[((size_t)b * TT + t) * 256 + d * HH + tid] = h;
        __syncthreads();          // h visible before next dot

        t += tstep;
        gcur = gnext;
    }

    asm volatile("barrier.cluster.arrive.aligned;" ::: "memory");
    asm volatile("barrier.cluster.wait.aligned;" ::: "memory");
}

// ---------------- mean over nodes (wide: 1024 threads, 4-way t-split) --------
__global__ __launch_bounds__(1024)
void agg_kernel(const float* __restrict__ lo, float* __restrict__ agg) {
    __shared__ float red[4][256];
    int b = blockIdx.x;
    int o = threadIdx.x & 255;
    int part = threadIdx.x >> 8;          // 0..3
    float s = 0.f;
    const float* lb = lo + (size_t)b * TT * 256 + o;
    #pragma unroll 4
    for (int t = part; t < TT; t += 4) s += lb[(size_t)t * 256];
    red[part][o] = s;
    __syncthreads();
    if (part == 0) {
        float v = (red[0][o] + red[1][o]) + (red[2][o] + red[3][o]);
        agg[b * 256 + o] = v * (1.0f / 256.0f);
    }
}

// ---------------- host launcher ----------------
extern "C" void kernel_launch(void* const* d_in, const int* in_sizes, int n_in,
                              void* d_out, int out_size)
{
    const float* x         = (const float*)d_in[0];
    const float* cheb_w    = (const float*)d_in[5];   // [2,256,256] = [512,256] stacked
    const float* cheb_b    = (const float*)d_in[6];
    const float* ln_cheb_g = (const float*)d_in[7];
    const float* ln_cheb_b = (const float*)d_in[8];
    const float* w_ih      = (const float*)d_in[9];   // [2,2,512,256]
    const float* w_hh      = (const float*)d_in[10];  // [2,2,512,128]
    const float* b_ih      = (const float*)d_in[11];  // [2,2,512]
    const float* b_hh      = (const float*)d_in[12];
    const float* ln_out_g  = (const float*)d_in[13];
    const float* ln_out_b  = (const float*)d_in[14];

    float* out = (float*)d_out;
    float* agg = out;                          // [8,256]
    float* tg  = out + BB * 256;               // [8,256,256]
    float* lo  = tg + BB * NN * NN;            // [8,256,256]

    float *S, *ctmp, *cout, *gin, *h1, *h2;
    cudaGetSymbolAddress((void**)&S,    g_S);
    cudaGetSymbolAddress((void**)&ctmp, g_ctmp);
    cudaGetSymbolAddress((void**)&cout, g_cout);
    cudaGetSymbolAddress((void**)&gin,  g_gin);
    cudaGetSymbolAddress((void**)&h1,   g_h1);
    cudaGetSymbolAddress((void**)&h2,   g_h2);

    // colsum + TG constant fill in one launch (8 + 512 blocks)
    colsum_fill_kernel<<<BB + 512, 256>>>(x, S, tg);

    // ChebConv: [x | (x+S/256)/2] @ [W0;W1], split-K4 partials; LN sums + bias
    gemm128_cheb<<<dim3(FF/128, ROWS/128, 4), 256>>>(x, S, cheb_w, ctmp, ROWS, FF);
    ln256_sum4_kernel<<<ROWS, 256>>>(ctmp, cheb_b, ln_cheb_g, ln_cheb_b, cout);

    // Layer 1: both-dir input gates, 128x64 tiles BK=32, 2 CTAs/SM (K=256)
    gemm64n<<<dim3(1024/64, ROWS/128), 256>>>(
        cout, w_ih, gin, ROWS, 1024, FF, b_ih, b_hh);
    lstm_scan_cluster<<<64, 128>>>(gin, w_hh, h1);

    // Layer 2 (K = 2H = 256)
    gemm64n<<<dim3(1024/64, ROWS/128), 256>>>(
        h1, w_ih + (size_t)2 * G4 * FF, gin, ROWS, 1024, 2 * HH,
        b_ih + 2 * G4, b_hh + 2 * G4);
    lstm_scan_cluster<<<64, 128>>>(gin, w_hh + (size_t)2 * G4 * HH, h2);

    // Final LN -> lstm_out, then node-mean -> agg
    ln256_kernel<<<ROWS, 256>>>(h2, ln_out_g, ln_out_b, lo);
    agg_kernel<<<BB, 1024>>>(lo, agg);
}

// round 17
// speedup vs baseline: 1.0117x; 1.0117x over previous
#include <cuda_runtime.h>
#include <cuda_bf16.h>
#include <cstdint>
#include <math.h>

// Problem constants
#define BB 8
#define NN 256
#define FF 256
#define HH 128
#define TT 256
#define G4 512           // 4*H gates
#define ROWS (BB*NN)     // 2048

// ---------------- scratch (device globals; no allocation allowed) ----------------
__device__ float g_S[BB*FF];                 // column sums
__device__ float g_ctmp[4*BB*NN*FF];         // cheb split-K partials (4)
__device__ float g_cout[BB*NN*FF];           // cheb out (layer1 input)
__device__ float g_gin[ROWS*1024];           // input gates, both dirs: [B*T][1024]
__device__ float g_h1[BB*NN*2*HH];           // layer1 concat output
__device__ float g_h2[BB*NN*2*HH];           // layer2 concat output

typedef unsigned long long ull;

// ---------------- small helpers ----------------
__device__ __forceinline__ float blocksum256(float v, volatile float* red) {
    #pragma unroll
    for (int o = 16; o; o >>= 1) v += __shfl_xor_sync(0xffffffffu, v, o);
    if ((threadIdx.x & 31) == 0) red[threadIdx.x >> 5] = v;
    __syncthreads();
    float s = 0.f;
    #pragma unroll
    for (int i = 0; i < 8; i++) s += red[i];
    return s;
}

__device__ __forceinline__ unsigned smem_u32(const void* p) {
    unsigned a;
    asm("{ .reg .u64 t; cvta.to.shared.u64 t, %1; cvt.u32.u64 %0, t; }"
        : "=r"(a) : "l"(p));
    return a;
}

// fast activations: __expf/__fdividef (rel err ~1e-7, fine vs 1e-3 threshold)
__device__ __forceinline__ float fsigmoid(float x) {
    return __fdividef(1.0f, 1.0f + __expf(-x));
}
__device__ __forceinline__ float ftanh(float x) {
    return 1.0f - __fdividef(2.0f, __expf(2.0f * x) + 1.0f);
}

#define MBAR_INIT(adr, cnt) \
    asm volatile("mbarrier.init.shared.b64 [%0], %1;" :: "r"(adr), "r"(cnt) : "memory")

#define MBAR_EXPECT_TX(adr, bytes) \
    asm volatile("mbarrier.arrive.expect_tx.shared.b64 _, [%0], %1;" \
                 :: "r"(adr), "r"(bytes) : "memory")

#define MBAR_WAIT_PARITY(adr, parity) do {                                        \
    unsigned _done;                                                               \
    asm volatile("{\n\t.reg .pred p;\n\t"                                         \
        "mbarrier.try_wait.parity.acquire.cluster.shared::cta.b64 p, [%1], %2;\n\t" \
        "selp.b32 %0, 1, 0, p;\n\t}"                                              \
        : "=r"(_done) : "r"(adr), "r"(parity) : "memory");                        \
    while (!_done) {                                                              \
        asm volatile("{\n\t.reg .pred p;\n\t"                                     \
            "mbarrier.try_wait.parity.acquire.cluster.shared::cta.b64 p, [%1], %2, 0x989680;\n\t" \
            "selp.b32 %0, 1, 0, p;\n\t}"                                          \
            : "=r"(_done) : "r"(adr), "r"(parity) : "memory");                    \
    } } while (0)

// ---------------- colsum + TG fill (merged launch) ----------------
__global__ void colsum_fill_kernel(const float* __restrict__ x, float* __restrict__ S,
                                   float* __restrict__ tg) {
    if (blockIdx.x < BB) {
        int b = blockIdx.x, f = threadIdx.x;
        float s = 0.f;
        const float* xb = x + (size_t)b * NN * FF + f;
        #pragma unroll 4
        for (int n = 0; n < NN; n++) s += xb[(size_t)n * FF];
        S[b * FF + f] = s;
    } else {
        // TG = exact constant (LayerNorm(1) degenerates; softmax of const rows)
        int i = (blockIdx.x - BB) * blockDim.x + threadIdx.x;
        const float q = 1.0f / 256.0f;
        ((float4*)tg)[i] = make_float4(q, q, q, q);
    }
}

// ---------------- 128(M)x64(N)-tile GEMM, BK=16, 2 CTAs/SM (gin GEMMs) --------
// R15 best-measured version (31.9us), restored verbatim after the BK=32 probe
// regressed (extra addr ALU + reg pressure). FROZEN.
__global__ __launch_bounds__(256, 2)
void gemm64n(const float* __restrict__ A, const float* __restrict__ B,
             float* __restrict__ C, int M, int N, int K,
             const float* __restrict__ bias0, const float* __restrict__ bias1)
{
    const int BK = 16;
    __shared__ float As[2][BK][128];
    __shared__ float Bs[2][BK][64];
    int tid = threadIdx.x;
    int tx = tid & 15, ty = tid >> 4;
    int bm = blockIdx.y * 128, bn = blockIdx.x * 64;

    int ar0 = (2 * tid) >> 2,     akf0 = ((2 * tid) & 3) * 4;
    int ar1 = (2 * tid + 1) >> 2, akf1 = ((2 * tid + 1) & 3) * 4;
    int br = tid >> 2, bkf = (tid & 3) * 4;

    const int ntiles = K / BK;
    float4 pa0, pa1, pb;
    auto loadTile = [&](int k0) {
        pa0 = *(const float4*)(A + (size_t)(bm + ar0) * K + k0 + akf0);
        pa1 = *(const float4*)(A + (size_t)(bm + ar1) * K + k0 + akf1);
        pb  = *(const float4*)(B + (size_t)(bn + br)  * K + k0 + bkf);
    };
    auto stash = [&](int st) {
        As[st][akf0 + 0][ar0] = pa0.x; As[st][akf0 + 1][ar0] = pa0.y;
        As[st][akf0 + 2][ar0] = pa0.z; As[st][akf0 + 3][ar0] = pa0.w;
        As[st][akf1 + 0][ar1] = pa1.x; As[st][akf1 + 1][ar1] = pa1.y;
        As[st][akf1 + 2][ar1] = pa1.z; As[st][akf1 + 3][ar1] = pa1.w;
        Bs[st][bkf + 0][br] = pb.x; Bs[st][bkf + 1][br] = pb.y;
        Bs[st][bkf + 2][br] = pb.z; Bs[st][bkf + 3][br] = pb.w;
    };

    loadTile(0);
    stash(0);
    __syncthreads();

    ull acc[4][4];
    #pragma unroll
    for (int i = 0; i < 4; i++)
        #pragma unroll
        for (int j = 0; j < 4; j++) acc[i][j] = 0ull;

    for (int kt = 0; kt < ntiles; kt++) {
        int st = kt & 1;
        if (kt + 1 < ntiles) loadTile((kt + 1) * BK);
        #pragma unroll
        for (int k = 0; k < BK; k++) {
            const float* ar = &As[st][k][ty * 8];
            const float* br2 = &Bs[st][k][tx * 4];
            ull ap[4], bd[4];
            #pragma unroll
            for (int i = 0; i < 4; i++) {
                float2 a2 = *(const float2*)(ar + 2 * i);
                asm("mov.b64 %0, {%1, %2};" : "=l"(ap[i]) : "f"(a2.x), "f"(a2.y));
            }
            #pragma unroll
            for (int i = 0; i < 2; i++) {
                float2 b2 = *(const float2*)(br2 + 2 * i);
                asm("mov.b64 %0, {%1, %1};" : "=l"(bd[2 * i])     : "f"(b2.x));
                asm("mov.b64 %0, {%1, %1};" : "=l"(bd[2 * i + 1]) : "f"(b2.y));
            }
            #pragma unroll
            for (int i = 0; i < 4; i++)
                #pragma unroll
                for (int j = 0; j < 4; j++)
                    asm("fma.rn.f32x2 %0, %1, %2, %3;"
                        : "=l"(acc[i][j]) : "l"(ap[i]), "l"(bd[j]), "l"(acc[i][j]));
        }
        if (kt + 1 < ntiles) stash(st ^ 1);
        __syncthreads();
    }

    float bsum[4];
    #pragma unroll
    for (int j = 0; j < 4; j++) {
        int col = bn + tx * 4 + j;
        bsum[j] = (bias0 ? bias0[col] : 0.f) + (bias1 ? bias1[col] : 0.f);
    }
    #pragma unroll
    for (int i = 0; i < 4; i++) {
        float lov[4], hiv[4];
        #pragma unroll
        for (int j = 0; j < 4; j++) {
            float lo, hi;
            asm("mov.b64 {%0, %1}, %2;" : "=f"(lo), "=f"(hi) : "l"(acc[i][j]));
            lov[j] = lo + bsum[j]; hiv[j] = hi + bsum[j];
        }
        int row = bm + ty * 8 + 2 * i;
        int col = bn + tx * 4;
        *(float4*)(C + (size_t)row * N + col)       = make_float4(lov[0], lov[1], lov[2], lov[3]);
        *(float4*)(C + (size_t)(row + 1) * N + col) = make_float4(hiv[0], hiv[1], hiv[2], hiv[3]);
    }
}

// ---------------- cheb split-K GEMM (R10 version, verbatim) -------
__global__ __launch_bounds__(256)
void gemm128_cheb(const float* __restrict__ A, const float* __restrict__ S,
                  const float* __restrict__ B, float* __restrict__ C,
                  int M, int N)
{
    const int BK = 16;
    __shared__ float As[2][BK][128];
    __shared__ float Bs[2][BK][128];
    int tid = threadIdx.x;
    int tx = tid & 15, ty = tid >> 4;
    int bm = blockIdx.y * 128, bn = blockIdx.x * 128;
    int kbeg = blockIdx.z * 128;
    C += (size_t)blockIdx.z * M * N;

    int r0 = (2 * tid) >> 2,     kf0 = ((2 * tid) & 3) * 4;
    int r1 = (2 * tid + 1) >> 2, kf1 = ((2 * tid + 1) & 3) * 4;
    int kr = tid >> 4, cq = (tid & 15) * 8;

    auto loadA4 = [&](int k0, int rr, int kf) -> float4 {
        int row = bm + rr;
        int kk = k0 + kf;
        if (kk >= 256) {
            kk -= 256;
            float4 xv = *(const float4*)(A + (size_t)row * 256 + kk);
            float4 sv = *(const float4*)(S + (row >> 8) * 256 + kk);
            const float q = 1.0f / 256.0f;
            return make_float4(0.5f * (xv.x + q * sv.x), 0.5f * (xv.y + q * sv.y),
                               0.5f * (xv.z + q * sv.z), 0.5f * (xv.w + q * sv.w));
        }
        return *(const float4*)(A + (size_t)row * 256 + kk);
    };
    auto stash = [&](int st, float4 a0, float4 a1, float4 b0, float4 b1) {
        As[st][kf0 + 0][r0] = a0.x; As[st][kf0 + 1][r0] = a0.y;
        As[st][kf0 + 2][r0] = a0.z; As[st][kf0 + 3][r0] = a0.w;
        As[st][kf1 + 0][r1] = a1.x; As[st][kf1 + 1][r1] = a1.y;
        As[st][kf1 + 2][r1] = a1.z; As[st][kf1 + 3][r1] = a1.w;
        *(float4*)&Bs[st][kr][cq]     = b0;
        *(float4*)&Bs[st][kr][cq + 4] = b1;
    };

    const int ntiles = 128 / BK;  // 8
    stash(0, loadA4(kbeg, r0, kf0), loadA4(kbeg, r1, kf1),
             *(const float4*)(B + (size_t)(kbeg + kr) * N + bn + cq),
             *(const float4*)(B + (size_t)(kbeg + kr) * N + bn + cq + 4));
    __syncthreads();

    ull acc[4][8];
    #pragma unroll
    for (int i = 0; i < 4; i++)
        #pragma unroll
        for (int j = 0; j < 8; j++) acc[i][j] = 0ull;

    for (int kt = 0; kt < ntiles; kt++) {
        int st = kt & 1;
        float4 an0, an1, bn0, bn1;
        if (kt + 1 < ntiles) {
            int k0 = kbeg + (kt + 1) * BK;
            an0 = loadA4(k0, r0, kf0); an1 = loadA4(k0, r1, kf1);
            bn0 = *(const float4*)(B + (size_t)(k0 + kr) * N + bn + cq);
            bn1 = *(const float4*)(B + (size_t)(k0 + kr) * N + bn + cq + 4);
        }
        #pragma unroll
        for (int k = 0; k < BK; k++) {
            const float* ar = &As[st][k][ty * 8];
            const float* br = &Bs[st][k][tx * 8];
            ull ap[4], bd[8];
            #pragma unroll
            for (int i = 0; i < 4; i++) {
                float2 a2 = *(const float2*)(ar + 2 * i);
                asm("mov.b64 %0, {%1, %2};" : "=l"(ap[i]) : "f"(a2.x), "f"(a2.y));
            }
            #pragma unroll
            for (int i = 0; i < 4; i++) {
                float2 b2 = *(const float2*)(br + 2 * i);
                asm("mov.b64 %0, {%1, %1};" : "=l"(bd[2 * i])     : "f"(b2.x));
                asm("mov.b64 %0, {%1, %1};" : "=l"(bd[2 * i + 1]) : "f"(b2.y));
            }
            #pragma unroll
            for (int i = 0; i < 4; i++)
                #pragma unroll
                for (int j = 0; j < 8; j++)
                    asm("fma.rn.f32x2 %0, %1, %2, %3;"
                        : "=l"(acc[i][j]) : "l"(ap[i]), "l"(bd[j]), "l"(acc[i][j]));
        }
        if (kt + 1 < ntiles)
            stash(st ^ 1, an0, an1, bn0, bn1);
        __syncthreads();
    }

    #pragma unroll
    for (int i = 0; i < 4; i++) {
        float lov[8], hiv[8];
        #pragma unroll
        for (int j = 0; j < 8; j++) {
            float lo, hi;
            asm("mov.b64 {%0, %1}, %2;" : "=f"(lo), "=f"(hi) : "l"(acc[i][j]));
            lov[j] = lo; hiv[j] = hi;
        }
        int row = bm + ty * 8 + 2 * i;
        int col = bn + tx * 8;
        *(float4*)(C + (size_t)row * N + col)           = make_float4(lov[0], lov[1], lov[2], lov[3]);
        *(float4*)(C + (size_t)row * N + col + 4)       = make_float4(lov[4], lov[5], lov[6], lov[7]);
        *(float4*)(C + (size_t)(row + 1) * N + col)     = make_float4(hiv[0], hiv[1], hiv[2], hiv[3]);
        *(float4*)(C + (size_t)(row + 1) * N + col + 4) = make_float4(hiv[4], hiv[5], hiv[6], hiv[7]);
    }
}

// ---------------- LayerNorm over 256 elems per row ----------------
__global__ __launch_bounds__(256)
void ln256_kernel(const float* __restrict__ x, const float* __restrict__ g,
                  const float* __restrict__ bt, float* __restrict__ y)
{
    __shared__ float red1[8];
    __shared__ float red2[8];
    size_t row = blockIdx.x;
    float v = x[row * 256 + threadIdx.x];
    float m = blocksum256(v, red1) * (1.0f / 256.0f);
    float d = v - m;
    float var = blocksum256(d * d, red2) * (1.0f / 256.0f);
    float r = rsqrtf(var + 1e-5f);
    y[row * 256 + threadIdx.x] = d * r * g[threadIdx.x] + bt[threadIdx.x];
}

// LN over sum of 4 split-K partials + bias (cheb path)
__global__ __launch_bounds__(256)
void ln256_sum4_kernel(const float* __restrict__ p, const float* __restrict__ bias,
                       const float* __restrict__ g, const float* __restrict__ bt,
                       float* __restrict__ y)
{
    __shared__ float red1[8];
    __shared__ float red2[8];
    size_t row = blockIdx.x;
    size_t idx = row * 256 + threadIdx.x;
    const size_t P = (size_t)ROWS * 256;
    float v = (p[idx] + p[idx + P]) + (p[idx + 2 * P] + p[idx + 3 * P]) + bias[threadIdx.x];
    float m = blocksum256(v, red1) * (1.0f / 256.0f);
    float d = v - m;
    float var = blocksum256(d * d, red2) * (1.0f / 256.0f);
    float r = rsqrtf(var + 1e-5f);
    y[idx] = d * r * g[threadIdx.x] + bt[threadIdx.x];
}

// ---------------- LSTM scan (R11 best-measured version, FROZEN) ----------------
__global__ void __launch_bounds__(128, 1) __cluster_dims__(4, 1, 1)
lstm_scan_cluster(const float* __restrict__ gin, const float* __restrict__ whh,
                  float* __restrict__ hout)
{
    __shared__ __align__(16) float hsh[2][HH];
    __shared__ __align__(16) float gb[2][G4];
    __shared__ __align__(8) ull mbar[2];

    int tid = threadIdx.x;
    unsigned rank;
    asm("mov.u32 %0, %%cluster_ctarank;" : "=r"(rank));
    int pair = blockIdx.x >> 2;
    int b = pair >> 1, d = pair & 1;
    int gate = (int)rank * 128 + tid;

    ull w[64];
    const float2* wrow = (const float2*)(whh + ((size_t)d * G4 + gate) * HH);
    #pragma unroll
    for (int i = 0; i < 64; i++) {
        float2 t2 = wrow[i];
        asm("mov.b64 %0, {%1, %2};" : "=l"(w[i]) : "f"(t2.x), "f"(t2.y));
    }

    const float* gp = gin + ((size_t)b * TT) * 1024 + d * 512 + gate;

    hsh[0][tid] = 0.f;

    unsigned hadr0 = smem_u32(&hsh[0][0]);
    unsigned hadr1 = smem_u32(&hsh[1][0]);
    unsigned mloc[2] = { smem_u32(&mbar[0]), smem_u32(&mbar[1]) };
    unsigned gadr[2][4], madr[2][4];
    #pragma unroll
    for (int par = 0; par < 2; par++) {
        unsigned la = smem_u32(&gb[par][gate]);
        #pragma unroll
        for (int peer = 0; peer < 4; peer++) {
            asm("mapa.shared::cluster.u32 %0, %1, %2;"
                : "=r"(gadr[par][peer]) : "r"(la), "r"(peer));
            asm("mapa.shared::cluster.u32 %0, %1, %2;"
                : "=r"(madr[par][peer]) : "r"(mloc[par]), "r"(peer));
        }
    }

    if (tid == 0) {
        MBAR_INIT(mloc[0], 1);
        MBAR_INIT(mloc[1], 1);
        MBAR_EXPECT_TX(mloc[0], 2048);   // step 0
        MBAR_EXPECT_TX(mloc[1], 2048);   // step 1
    }
    __syncthreads();
    asm volatile("barrier.cluster.arrive.aligned;" ::: "memory");
    asm volatile("barrier.cluster.wait.aligned;" ::: "memory");

    int ph0 = 0, ph1 = 0;
    float c = 0.f;
    int t = d ? (TT - 1) : 0;
    const int tstep = d ? -1 : 1;
    float gcur = gp[(size_t)t * 1024];

    for (int s = 0; s < TT; s++) {
        int par = s & 1;
        unsigned hadr = par ? hadr1 : hadr0;   // dot reads hsh[s&1]

        ull a0 = 0ull, a1 = 0ull, a2 = 0ull, a3 = 0ull;
        #pragma unroll
        for (int i = 0; i < 64; i += 4) {
            ull h0, h1, h2, h3;
            asm volatile("ld.shared.v2.b64 {%0, %1}, [%2];"
                         : "=l"(h0), "=l"(h1) : "r"(hadr + i * 8));
            asm volatile("ld.shared.v2.b64 {%0, %1}, [%2];"
                         : "=l"(h2), "=l"(h3) : "r"(hadr + i * 8 + 16));
            asm("fma.rn.f32x2 %0, %1, %2, %3;" : "=l"(a0) : "l"(w[i + 0]), "l"(h0), "l"(a0));
            asm("fma.rn.f32x2 %0, %1, %2, %3;" : "=l"(a1) : "l"(w[i + 1]), "l"(h1), "l"(a1));
            asm("fma.rn.f32x2 %0, %1, %2, %3;" : "=l"(a2) : "l"(w[i + 2]), "l"(h2), "l"(a2));
            asm("fma.rn.f32x2 %0, %1, %2, %3;" : "=l"(a3) : "l"(w[i + 3]), "l"(h3), "l"(a3));
        }
        float x0, y0, x1, y1, x2, y2, x3, y3;
        asm("mov.b64 {%0, %1}, %2;" : "=f"(x0), "=f"(y0) : "l"(a0));
        asm("mov.b64 {%0, %1}, %2;" : "=f"(x1), "=f"(y1) : "l"(a1));
        asm("mov.b64 {%0, %1}, %2;" : "=f"(x2), "=f"(y2) : "l"(a2));
        asm("mov.b64 {%0, %1}, %2;" : "=f"(x3), "=f"(y3) : "l"(a3));
        float v = gcur + ((x0 + y0) + (x1 + y1)) + ((x2 + y2) + (x3 + y3));

        unsigned vbits = __float_as_uint(v);
        #pragma unroll
        for (int peer = 0; peer < 4; peer++) {
            asm volatile(
                "st.async.shared::cluster.mbarrier::complete_tx::bytes.b32 [%0], %1, [%2];"
                :: "r"(gadr[par][peer]), "r"(vbits), "r"(madr[par][peer]) : "memory");
        }

        float gnext = 0.f;
        if (s + 1 < TT) gnext = gp[(size_t)(t + tstep) * 1024];

        unsigned mb = par ? mloc[1] : mloc[0];
        int phv = par ? ph1 : ph0;
        MBAR_WAIT_PARITY(mb, phv);
        if (par) ph1 ^= 1; else ph0 ^= 1;
        if (tid == 0 && s + 2 < TT) MBAR_EXPECT_TX(mb, 2048);

        float ig = fsigmoid(gb[par][tid]);
        float fg = fsigmoid(gb[par][tid + 128]);
        float gg = ftanh(gb[par][tid + 256]);
        float og = fsigmoid(gb[par][tid + 384]);
        c = fg * c + ig * gg;
        float h = og * ftanh(c);
        hsh[par ^ 1][tid] = h;    // write the OTHER buffer (next step reads it)
        if (rank == 0)
            hout[((size_t)b * TT + t) * 256 + d * HH + tid] = h;
        __syncthreads();          // h visible before next dot

        t += tstep;
        gcur = gnext;
    }

    asm volatile("barrier.cluster.arrive.aligned;" ::: "memory");
    asm volatile("barrier.cluster.wait.aligned;" ::: "memory");
}

// ---------------- mean over nodes (wide: 1024 threads, 4-way t-split) --------
__global__ __launch_bounds__(1024)
void agg_kernel(const float* __restrict__ lo, float* __restrict__ agg) {
    __shared__ float red[4][256];
    int b = blockIdx.x;
    int o = threadIdx.x & 255;
    int part = threadIdx.x >> 8;          // 0..3
    float s = 0.f;
    const float* lb = lo + (size_t)b * TT * 256 + o;
    #pragma unroll 4
    for (int t = part; t < TT; t += 4) s += lb[(size_t)t * 256];
    red[part][o] = s;
    __syncthreads();
    if (part == 0) {
        float v = (red[0][o] + red[1][o]) + (red[2][o] + red[3][o]);
        agg[b * 256 + o] = v * (1.0f / 256.0f);
    }
}

// ---------------- host launcher ----------------
extern "C" void kernel_launch(void* const* d_in, const int* in_sizes, int n_in,
                              void* d_out, int out_size)
{
    const float* x         = (const float*)d_in[0];
    const float* cheb_w    = (const float*)d_in[5];   // [2,256,256] = [512,256] stacked
    const float* cheb_b    = (const float*)d_in[6];
    const float* ln_cheb_g = (const float*)d_in[7];
    const float* ln_cheb_b = (const float*)d_in[8];
    const float* w_ih      = (const float*)d_in[9];   // [2,2,512,256]
    const float* w_hh      = (const float*)d_in[10];  // [2,2,512,128]
    const float* b_ih      = (const float*)d_in[11];  // [2,2,512]
    const float* b_hh      = (const float*)d_in[12];
    const float* ln_out_g  = (const float*)d_in[13];
    const float* ln_out_b  = (const float*)d_in[14];

    float* out = (float*)d_out;
    float* agg = out;                          // [8,256]
    float* tg  = out + BB * 256;               // [8,256,256]
    float* lo  = tg + BB * NN * NN;            // [8,256,256]

    float *S, *ctmp, *cout, *gin, *h1, *h2;
    cudaGetSymbolAddress((void**)&S,    g_S);
    cudaGetSymbolAddress((void**)&ctmp, g_ctmp);
    cudaGetSymbolAddress((void**)&cout, g_cout);
    cudaGetSymbolAddress((void**)&gin,  g_gin);
    cudaGetSymbolAddress((void**)&h1,   g_h1);
    cudaGetSymbolAddress((void**)&h2,   g_h2);

    // colsum + TG constant fill in one launch (8 + 512 blocks)
    colsum_fill_kernel<<<BB + 512, 256>>>(x, S, tg);

    // ChebConv: [x | (x+S/256)/2] @ [W0;W1], split-K4 partials; LN sums + bias
    gemm128_cheb<<<dim3(FF/128, ROWS/128, 4), 256>>>(x, S, cheb_w, ctmp, ROWS, FF);
    ln256_sum4_kernel<<<ROWS, 256>>>(ctmp, cheb_b, ln_cheb_g, ln_cheb_b, cout);

    // Layer 1: both-dir input gates, 128x64 tiles BK=16, 2 CTAs/SM (K=256)
    gemm64n<<<dim3(1024/64, ROWS/128), 256>>>(
        cout, w_ih, gin, ROWS, 1024, FF, b_ih, b_hh);
    lstm_scan_cluster<<<64, 128>>>(gin, w_hh, h1);

    // Layer 2 (K = 2H = 256)
    gemm64n<<<dim3(1024/64, ROWS/128), 256>>>(
        h1, w_ih + (size_t)2 * G4 * FF, gin, ROWS, 1024, 2 * HH,
        b_ih + 2 * G4, b_hh + 2 * G4);
    lstm_scan_cluster<<<64, 128>>>(gin, w_hh + (size_t)2 * G4 * HH, h2);

    // Final LN -> lstm_out, then node-mean -> agg
    ln256_kernel<<<ROWS, 256>>>(h2, ln_out_g, ln_out_b, lo);
    agg_kernel<<<BB, 1024>>>(lo, agg);
}